// round 6
// baseline (speedup 1.0000x reference)
#include <cuda_runtime.h>
#include <cuda_fp16.h>
#include <math.h>

#define NMAX 100000
#define EMAX 1700000
#define HID  64
#define NCLS 40
#define GRED 256
#define SCAN_B 1024

// -------- scratch (device globals: no allocations allowed) --------
__device__ int      g_rowptr[NMAX + 1];
__device__ int      g_cnt[NMAX];        // histogram counts, then scatter cursor
__device__ int      g_csr[EMAX];        // src indices bucketed by dst
__device__ unsigned g_scan_state[128];  // lookback: flag(2b)<<30 | value
__device__ int      g_ctr;              // k_loss completion counter
__device__ __half   g_buf [NMAX * HID]; // transformed features (X@W), fp16, stride 64
__device__ float    g_hbuf[NMAX * HID]; // layer activations, fp32
__device__ float    g_W2p[64 * 64];     // W2 zero-padded to 64 cols
__device__ float    g_pM[GRED * NCLS];
__device__ float    g_pS[GRED * NCLS];
__device__ float    g_logZ[NCLS];
__device__ float    g_loss[2];

// ---------------------- fast exp (FMA pipe, x <= 0) ------------------
__device__ __forceinline__ float fexp(float x) {
    x = fmaxf(x, -80.0f);
    float y = x * 1.44269504f;
    int   ni = __float2int_rn(y);
    float f = y - (float)ni;
    float g = f * 0.69314718f;
    float p = fmaf(g, 1.3888889e-3f, 8.3333333e-3f);
    p = fmaf(p, g, 4.1666667e-2f);
    p = fmaf(p, g, 1.6666667e-1f);
    p = fmaf(p, g, 0.5f);
    p = fmaf(p, g, 1.0f);
    p = fmaf(p, g, 1.0f);
    return p * __int_as_float((ni + 127) << 23);
}

// ------------------------------- init -------------------------------
__global__ void k_init(int N) {
    int i = blockIdx.x * blockDim.x + threadIdx.x;
    if (i < N) g_cnt[i] = 0;
    if (i < 128) g_scan_state[i] = 0u;
    if (i == 0) { g_loss[0] = 0.f; g_loss[1] = 0.f; g_ctr = 0; }
}

// --------------------------- CSR build ------------------------------
__global__ void k_hist(const int* __restrict__ dst, int E) {
    for (int e = blockIdx.x * blockDim.x + threadIdx.x; e < E;
         e += gridDim.x * blockDim.x)
        atomicAdd(&g_cnt[dst[e]], 1);
}

// single-pass exclusive scan with decoupled lookback (unsigned flags!)
// flag: 0 = empty, 1 = partial aggregate, 2 = inclusive prefix
__global__ void k_scan(int N) {
    __shared__ int sh[SCAN_B];
    __shared__ int s_prefix;
    const unsigned FULL = 0xffffffffu;
    int b = blockIdx.x;
    int i = b * SCAN_B + threadIdx.x;
    int c = (i < N) ? g_cnt[i] : 0;
    sh[threadIdx.x] = c;
    __syncthreads();
    for (int off = 1; off < SCAN_B; off <<= 1) {
        int t = (threadIdx.x >= off) ? sh[threadIdx.x - off] : 0;
        __syncthreads();
        sh[threadIdx.x] += t;
        __syncthreads();
    }
    int incl = sh[threadIdx.x];
    int agg  = sh[SCAN_B - 1];

    if (threadIdx.x == 0) {
        if (b == 0) {
            s_prefix = 0;
            atomicExch(&g_scan_state[0], 0x80000000u | (unsigned)agg);
        } else {
            atomicExch(&g_scan_state[b], 0x40000000u | (unsigned)agg);
        }
    }
    if (b > 0 && threadIdx.x < 32) {
        int lane = threadIdx.x;
        int prefix = 0;
        int look = b - 1;
        while (true) {
            int idxb = look - lane;
            unsigned st;
            if (idxb >= 0) {
                do { st = atomicAdd(&g_scan_state[idxb], 0u); } while ((st >> 30) == 0u);
            } else {
                st = 0x80000000u;   // virtual inclusive 0
            }
            int val = (int)(st & 0x3FFFFFFFu);
            unsigned m2 = __ballot_sync(FULL, (st >> 30) == 2u);
            if (m2 == 0u) {                       // all partial
                int s = val;
                for (int o = 16; o; o >>= 1) s += __shfl_xor_sync(FULL, s, o);
                prefix += s;
                look -= 32;
            } else {
                int firstIncl = __ffs(m2) - 1;    // nearest inclusive
                int s = (lane <= firstIncl) ? val : 0;
                for (int o = 16; o; o >>= 1) s += __shfl_xor_sync(FULL, s, o);
                prefix += s;
                break;
            }
        }
        if (lane == 0) {
            atomicExch(&g_scan_state[b], 0x80000000u | (unsigned)(prefix + agg));
            s_prefix = prefix;
        }
    }
    __syncthreads();
    int base = s_prefix;
    int excl = base + incl - c;
    if (i < N) { g_rowptr[i] = excl; g_cnt[i] = excl; }
    if (i == N - 1) g_rowptr[N] = base + incl;
}

__global__ void k_scatter(const int* __restrict__ src,
                          const int* __restrict__ dst, int E) {
    for (int e = blockIdx.x * blockDim.x + threadIdx.x; e < E;
         e += gridDim.x * blockDim.x) {
        int pos = atomicAdd(&g_cnt[dst[e]], 1);
        g_csr[pos] = src[e];
    }
}

// pad W2 [64][40] -> g_W2p [64][64] (cols 40..63 zero)
__global__ void k_w2pad(const float* __restrict__ W2) {
    int i = blockIdx.x * blockDim.x + threadIdx.x;
    if (i < 64 * 64) {
        int k = i >> 6, j = i & 63;
        g_W2p[i] = (j < NCLS) ? W2[k * NCLS + j] : 0.f;
    }
}

// --------------------- register-tiled GEMM -------------------------
// Y[N, 64(fp16 stride)] = X[N,64] @ W[64,64]. 128 rows/block, 128 threads.
__global__ void k_gemm_rt(const float* __restrict__ X, const float* __restrict__ W,
                          __half* __restrict__ Y, int N) {
    constexpr int KOUT = 64;
    constexpr int CPN = 8;
    constexpr int SXS = 68;
    extern __shared__ float smem[];
    float* sX = smem;                 // [128][68]
    float* sW = smem + 128 * SXS;     // [64][64]
    int tid = threadIdx.x;
    int rbase = blockIdx.x * 128;

    const float4* X4 = (const float4*)X;
    for (int i = tid; i < 2048; i += 128) {
        int row = i >> 4, k4 = i & 15;
        float4 v = make_float4(0.f, 0.f, 0.f, 0.f);
        if (rbase + row < N) v = X4[(size_t)(rbase + row) * 16 + k4];
        float* p = sX + row * SXS + k4 * 4;
        p[0] = v.x; p[1] = v.y; p[2] = v.z; p[3] = v.w;
    }
    for (int i = tid; i < 64 * KOUT / 4; i += 128)
        ((float4*)sW)[i] = ((const float4*)W)[i];
    __syncthreads();

    int ty = tid >> 3, tx = tid & 7;
    const float* ap = sX + (ty * 8) * SXS;
    const float* wp = sW + tx * CPN;

    float acc[8][CPN];
#pragma unroll
    for (int i = 0; i < 8; i++)
#pragma unroll
        for (int j = 0; j < CPN; j++) acc[i][j] = 0.f;

#pragma unroll 4
    for (int kk = 0; kk < 32; kk++) {
        int k = kk * 2;
        float2 a[8];
#pragma unroll
        for (int i = 0; i < 8; i++)
            a[i] = *(const float2*)(ap + i * SXS + k);
        float w0[CPN], w1[CPN];
#pragma unroll
        for (int j = 0; j < CPN; j++) {
            w0[j] = wp[(size_t)k * KOUT + j];
            w1[j] = wp[(size_t)(k + 1) * KOUT + j];
        }
#pragma unroll
        for (int i = 0; i < 8; i++)
#pragma unroll
            for (int j = 0; j < CPN; j++) {
                acc[i][j] = fmaf(a[i].x, w0[j], acc[i][j]);
                acc[i][j] = fmaf(a[i].y, w1[j], acc[i][j]);
            }
    }

#pragma unroll
    for (int i = 0; i < 8; i++) {
        int row = rbase + ty * 8 + i;
        if (row >= N) break;
        __half* yr = Y + (size_t)row * 64 + tx * CPN;
        union { uint4 u; __half2 h[4]; } pk;
#pragma unroll
        for (int j = 0; j < 4; j++)
            pk.h[j] = __floats2half2_rn(acc[i][2 * j], acc[i][2 * j + 1]);
        *(uint4*)yr = pk.u;
    }
}

// ------------------------------ SpMM --------------------------------
// 4 edges per LDG.128: 8 lanes x uint4 = one 128B fp16 row; e4 = lane>>3
// selects which of 4 edges this lane gathers. Final shfl_xor(8,16) folds.
template <int OUTW, bool RELU>
__global__ void k_spmm4(const __half* __restrict__ g,
                        const float* __restrict__ bias,
                        float* __restrict__ out, int N) {
    const unsigned FULL = 0xffffffffu;
    int w = (blockIdx.x * blockDim.x + threadIdx.x) >> 5;
    int lane = threadIdx.x & 31;
    if (w >= N) return;
    int beg = g_rowptr[w], end = g_rowptr[w + 1];
    int e4 = lane >> 3;        // 0..3: edge slot
    int c8 = lane & 7;         // col group (8 halfs)
    float acc[8];
#pragma unroll
    for (int j = 0; j < 8; j++) acc[j] = 0.f;

    int i = beg;
    for (; i + 8 <= end; i += 8) {
        int idx = g_csr[i + (lane & 7)];
        int s0 = __shfl_sync(FULL, idx, e4);
        int s1 = __shfl_sync(FULL, idx, 4 + e4);
        uint4 v0 = *(const uint4*)(g + (size_t)s0 * 64 + c8 * 8);
        uint4 v1 = *(const uint4*)(g + (size_t)s1 * 64 + c8 * 8);
        const __half2* h0 = (const __half2*)&v0;
        const __half2* h1 = (const __half2*)&v1;
#pragma unroll
        for (int q = 0; q < 4; q++) {
            float2 f0 = __half22float2(h0[q]);
            float2 f1 = __half22float2(h1[q]);
            acc[2 * q]     += f0.x + f1.x;
            acc[2 * q + 1] += f0.y + f1.y;
        }
    }
    if (i + 4 <= end) {
        int idx = g_csr[i + (lane & 3)];
        int s0 = __shfl_sync(FULL, idx, e4);
        uint4 v0 = *(const uint4*)(g + (size_t)s0 * 64 + c8 * 8);
        const __half2* h0 = (const __half2*)&v0;
#pragma unroll
        for (int q = 0; q < 4; q++) {
            float2 f0 = __half22float2(h0[q]);
            acc[2 * q]     += f0.x;
            acc[2 * q + 1] += f0.y;
        }
        i += 4;
    }
    for (; i < end; i++) {            // tail 0..3 edges, count once (e4==0)
        int s = g_csr[i];
        uint4 v = *(const uint4*)(g + (size_t)s * 64 + c8 * 8);
        if (e4 == 0) {
            const __half2* h = (const __half2*)&v;
#pragma unroll
            for (int q = 0; q < 4; q++) {
                float2 f = __half22float2(h[q]);
                acc[2 * q]     += f.x;
                acc[2 * q + 1] += f.y;
            }
        }
    }
    // fold the 4 edge slots
#pragma unroll
    for (int j = 0; j < 8; j++) {
        acc[j] += __shfl_xor_sync(FULL, acc[j], 8);
        acc[j] += __shfl_xor_sync(FULL, acc[j], 16);
    }
    if (e4 == 0 && (OUTW == 64 || c8 < OUTW / 8)) {
        float4 b0 = ((const float4*)bias)[c8 * 2];
        float4 b1 = ((const float4*)bias)[c8 * 2 + 1];
        float4 r0 = make_float4(acc[0] + b0.x, acc[1] + b0.y, acc[2] + b0.z, acc[3] + b0.w);
        float4 r1 = make_float4(acc[4] + b1.x, acc[5] + b1.y, acc[6] + b1.z, acc[7] + b1.w);
        if (RELU) {
            r0.x = fmaxf(r0.x, 0.f); r0.y = fmaxf(r0.y, 0.f);
            r0.z = fmaxf(r0.z, 0.f); r0.w = fmaxf(r0.w, 0.f);
            r1.x = fmaxf(r1.x, 0.f); r1.y = fmaxf(r1.y, 0.f);
            r1.z = fmaxf(r1.z, 0.f); r1.w = fmaxf(r1.w, 0.f);
        }
        float* orow = out + (size_t)w * OUTW + c8 * 8;
        ((float4*)orow)[0] = r0;
        ((float4*)orow)[1] = r1;
    }
}

// ---------------------- axis-0 log-softmax + loss -------------------
__device__ __forceinline__ void msmerge(float& M, float& S, float m2, float s2) {
    if (m2 > M) { S = S * fexp(M - m2) + s2; M = m2; }
    else if (m2 > -INFINITY) S += s2 * fexp(m2 - M);
}

__global__ void k_colreduce(const float* __restrict__ rep, int N) {
    int col = threadIdx.x % NCLS;
    int sub = threadIdx.x / NCLS;
    float m = -INFINITY, s = 0.f;
    for (int r = blockIdx.x * 8 + sub; r < N; r += 8 * gridDim.x) {
        float x = rep[(size_t)r * NCLS + col];
        if (x > m) { s = s * fexp(m - x) + 1.f; m = x; }
        else s += fexp(x - m);
    }
    __shared__ float shm[320], shs[320];
    shm[threadIdx.x] = m; shs[threadIdx.x] = s;
    __syncthreads();
    if (sub == 0) {
        float M = m, S = s;
        for (int k = 1; k < 8; k++) msmerge(M, S, shm[k * NCLS + col], shs[k * NCLS + col]);
        g_pM[blockIdx.x * NCLS + col] = M;
        g_pS[blockIdx.x * NCLS + col] = S;
    }
}

__global__ void k_colfinal() {
    int col = threadIdx.x;
    if (col >= NCLS) return;
    float M = -INFINITY, S = 0.f;
    for (int b = 0; b < GRED; b++) msmerge(M, S, g_pM[b * NCLS + col], g_pS[b * NCLS + col]);
    g_logZ[col] = M + logf(S);
}

__global__ void k_loss(const float* __restrict__ rep,
                       const int* __restrict__ labels,
                       const int* __restrict__ mask, int N,
                       float* __restrict__ out_loss) {
    float lp = 0.f, lm = 0.f;
    for (int n = blockIdx.x * blockDim.x + threadIdx.x; n < N;
         n += gridDim.x * blockDim.x) {
        if (mask[n] != 0) {
            int l = labels[n];
            lp += rep[(size_t)n * NCLS + l] - g_logZ[l];
            lm += 1.f;
        }
    }
    __shared__ float sp[256], sm[256];
    sp[threadIdx.x] = lp; sm[threadIdx.x] = lm;
    __syncthreads();
    for (int off = 128; off > 0; off >>= 1) {
        if (threadIdx.x < off) {
            sp[threadIdx.x] += sp[threadIdx.x + off];
            sm[threadIdx.x] += sm[threadIdx.x + off];
        }
        __syncthreads();
    }
    if (threadIdx.x == 0) {
        atomicAdd(&g_loss[0], sp[0]);
        atomicAdd(&g_loss[1], sm[0]);
        __threadfence();
        int done = atomicAdd(&g_ctr, 1);
        if (done == gridDim.x - 1 && out_loss)
            *out_loss = -g_loss[0] / g_loss[1];
    }
}

// ------------------------------ launch ------------------------------
extern "C" void kernel_launch(void* const* d_in, const int* in_sizes, int n_in,
                              void* d_out, int out_size) {
    const float* features = (const float*)d_in[0];
    const float* W0 = (const float*)d_in[1];
    const float* b0 = (const float*)d_in[2];
    const float* W1 = (const float*)d_in[3];
    const float* b1 = (const float*)d_in[4];
    const float* W2 = (const float*)d_in[5];
    const float* b2 = (const float*)d_in[6];
    const int*   src = (const int*)d_in[7];
    const int*   dst = (const int*)d_in[8];
    const int*   labels = (const int*)d_in[9];
    const int*   mask = (const int*)d_in[10];

    int N = in_sizes[0] / HID;
    int E = in_sizes[7];
    if (N > NMAX) N = NMAX;
    if (E > EMAX) E = EMAX;

    float* rep = (float*)d_out;
    float* lossptr = (out_size > N * NCLS) ? rep + (size_t)N * NCLS : nullptr;

    __half* gbuf; cudaGetSymbolAddress((void**)&gbuf, g_buf);
    float*  hbuf; cudaGetSymbolAddress((void**)&hbuf, g_hbuf);
    float*  w2p;  cudaGetSymbolAddress((void**)&w2p,  g_W2p);

    const int SM64 = (128 * 68 + 64 * 64) * 4;
    cudaFuncSetAttribute(k_gemm_rt, cudaFuncAttributeMaxDynamicSharedMemorySize, SM64);

    int NB = (N + SCAN_B - 1) / SCAN_B;
    int gemmBlocks = (N + 127) / 128;
    int spmmBlocks = (N * 32 + 255) / 256;

    // CSR build; k_scatter at launch slot 3 (ncu telemetry)
    k_init<<<(N + 255) / 256, 256>>>(N);
    k_hist<<<2048, 256>>>(dst, E);
    k_scan<<<NB, SCAN_B>>>(N);
    k_scatter<<<2048, 256>>>(src, dst, E);
    k_w2pad<<<16, 256>>>(W2);

    // Layer 0
    k_gemm_rt<<<gemmBlocks, 128, SM64>>>(features, W0, gbuf, N);
    k_spmm4<64, true><<<spmmBlocks, 256>>>(gbuf, b0, hbuf, N);
    // Layer 1
    k_gemm_rt<<<gemmBlocks, 128, SM64>>>(hbuf, W1, gbuf, N);
    k_spmm4<64, true><<<spmmBlocks, 256>>>(gbuf, b1, hbuf, N);
    // Layer 2 (W2 padded to 64 cols; output 40-wide)
    k_gemm_rt<<<gemmBlocks, 128, SM64>>>(hbuf, w2p, gbuf, N);
    k_spmm4<40, false><<<spmmBlocks, 256>>>(gbuf, b2, rep, N);

    // axis-0 log-softmax + NLL loss
    k_colreduce<<<GRED, 320>>>(rep, N);
    k_colfinal<<<1, 64>>>();
    k_loss<<<256, 256>>>(rep, labels, mask, N, lossptr);
}

// round 8
// speedup vs baseline: 1.1281x; 1.1281x over previous
#include <cuda_runtime.h>
#include <cuda_fp16.h>
#include <math.h>

#define NMAX 100000
#define EMAX 1700000
#define HID  64
#define NCLS 40
#define GRED 256
#define SCAN_B 1024

// -------- scratch (device globals: no allocations allowed) --------
__device__ int      g_rowptr[NMAX + 1];
__device__ int      g_cnt[NMAX];        // histogram counts, then scatter cursor
__device__ int      g_csr[EMAX];        // src indices bucketed by dst
__device__ unsigned g_scan_state[128];  // lookback: flag(2b)<<30 | value
__device__ int      g_ctr;              // k_loss completion counter
__device__ __half   g_buf [NMAX * HID]; // transformed features (X@W), fp16, stride 64
__device__ float    g_hbuf[NMAX * HID]; // layer activations, fp32
__device__ float    g_W2p[64 * 64];     // W2 zero-padded to 64 cols
__device__ float    g_pM[GRED * NCLS];
__device__ float    g_pS[GRED * NCLS];
__device__ float    g_logZ[NCLS];
__device__ float    g_loss[2];

// ---------------------- fast exp (FMA pipe, x <= 0) ------------------
__device__ __forceinline__ float fexp(float x) {
    x = fmaxf(x, -80.0f);
    float y = x * 1.44269504f;
    int   ni = __float2int_rn(y);
    float f = y - (float)ni;
    float g = f * 0.69314718f;
    float p = fmaf(g, 1.3888889e-3f, 8.3333333e-3f);
    p = fmaf(p, g, 4.1666667e-2f);
    p = fmaf(p, g, 1.6666667e-1f);
    p = fmaf(p, g, 0.5f);
    p = fmaf(p, g, 1.0f);
    p = fmaf(p, g, 1.0f);
    return p * __int_as_float((ni + 127) << 23);
}

// ------------------------------- init -------------------------------
__global__ void k_init(int N) {
    int i = blockIdx.x * blockDim.x + threadIdx.x;
    if (i < N) g_cnt[i] = 0;
    if (i < 128) g_scan_state[i] = 0u;
    if (i == 0) { g_loss[0] = 0.f; g_loss[1] = 0.f; g_ctr = 0; }
}

// --------------------------- CSR build ------------------------------
__global__ void k_hist(const int* __restrict__ dst, int E) {
    int stride = gridDim.x * blockDim.x;
    int i = blockIdx.x * blockDim.x + threadIdx.x;
    int E4 = E >> 2;
    for (int e = i; e < E4; e += stride) {
        int4 d = ((const int4*)dst)[e];
        atomicAdd(&g_cnt[d.x], 1);
        atomicAdd(&g_cnt[d.y], 1);
        atomicAdd(&g_cnt[d.z], 1);
        atomicAdd(&g_cnt[d.w], 1);
    }
    int tail = E4 * 4 + i;
    if (tail < E) atomicAdd(&g_cnt[dst[tail]], 1);
}

// single-pass exclusive scan with decoupled lookback (unsigned flags)
__global__ void k_scan(int N) {
    __shared__ int sh[SCAN_B];
    __shared__ int s_prefix;
    const unsigned FULL = 0xffffffffu;
    int b = blockIdx.x;
    int i = b * SCAN_B + threadIdx.x;
    int c = (i < N) ? g_cnt[i] : 0;
    sh[threadIdx.x] = c;
    __syncthreads();
    for (int off = 1; off < SCAN_B; off <<= 1) {
        int t = (threadIdx.x >= off) ? sh[threadIdx.x - off] : 0;
        __syncthreads();
        sh[threadIdx.x] += t;
        __syncthreads();
    }
    int incl = sh[threadIdx.x];
    int agg  = sh[SCAN_B - 1];

    if (threadIdx.x == 0) {
        if (b == 0) {
            s_prefix = 0;
            atomicExch(&g_scan_state[0], 0x80000000u | (unsigned)agg);
        } else {
            atomicExch(&g_scan_state[b], 0x40000000u | (unsigned)agg);
        }
    }
    if (b > 0 && threadIdx.x < 32) {
        int lane = threadIdx.x;
        int prefix = 0;
        int look = b - 1;
        while (true) {
            int idxb = look - lane;
            unsigned st;
            if (idxb >= 0) {
                do { st = atomicAdd(&g_scan_state[idxb], 0u); } while ((st >> 30) == 0u);
            } else {
                st = 0x80000000u;
            }
            int val = (int)(st & 0x3FFFFFFFu);
            unsigned m2 = __ballot_sync(FULL, (st >> 30) == 2u);
            if (m2 == 0u) {
                int s = val;
                for (int o = 16; o; o >>= 1) s += __shfl_xor_sync(FULL, s, o);
                prefix += s;
                look -= 32;
            } else {
                int firstIncl = __ffs(m2) - 1;
                int s = (lane <= firstIncl) ? val : 0;
                for (int o = 16; o; o >>= 1) s += __shfl_xor_sync(FULL, s, o);
                prefix += s;
                break;
            }
        }
        if (lane == 0) {
            atomicExch(&g_scan_state[b], 0x80000000u | (unsigned)(prefix + agg));
            s_prefix = prefix;
        }
    }
    __syncthreads();
    int base = s_prefix;
    int excl = base + incl - c;
    if (i < N) { g_rowptr[i] = excl; g_cnt[i] = excl; }
    if (i == N - 1) g_rowptr[N] = base + incl;
}

__global__ void k_scatter(const int* __restrict__ src,
                          const int* __restrict__ dst, int E) {
    int stride = gridDim.x * blockDim.x;
    int i = blockIdx.x * blockDim.x + threadIdx.x;
    int E4 = E >> 2;
    for (int e = i; e < E4; e += stride) {
        int4 d = ((const int4*)dst)[e];
        int4 s = ((const int4*)src)[e];
        g_csr[atomicAdd(&g_cnt[d.x], 1)] = s.x;
        g_csr[atomicAdd(&g_cnt[d.y], 1)] = s.y;
        g_csr[atomicAdd(&g_cnt[d.z], 1)] = s.z;
        g_csr[atomicAdd(&g_cnt[d.w], 1)] = s.w;
    }
    int tail = E4 * 4 + i;
    if (tail < E)
        g_csr[atomicAdd(&g_cnt[dst[tail]], 1)] = src[tail];
}

// pad W2 [64][40] -> g_W2p [64][64] (cols 40..63 zero)
__global__ void k_w2pad(const float* __restrict__ W2) {
    int i = blockIdx.x * blockDim.x + threadIdx.x;
    if (i < 64 * 64) {
        int k = i >> 6, j = i & 63;
        g_W2p[i] = (j < NCLS) ? W2[k * NCLS + j] : 0.f;
    }
}

// --------------------- register-tiled GEMM -------------------------
// Y[N, 64(fp16 stride)] = X[N,64] @ W[64,64]. 128 rows/block, 128 threads.
// sX row stride 66 (even -> float2 aligned). Thread ty handles rows
// ty + 16*i: warp's 4 ty-groups differ by 66 ≡ 2 (mod 32) banks ->
// LDS.64 hits disjoint bank pairs, conflict-free.
__global__ void k_gemm_rt(const float* __restrict__ X, const float* __restrict__ W,
                          __half* __restrict__ Y, int N) {
    constexpr int KOUT = 64;
    constexpr int SXS = 66;
    extern __shared__ float smem[];
    float* sX = smem;                 // [128][66]
    float* sW = smem + 128 * SXS;     // [64][64]
    int tid = threadIdx.x;
    int rbase = blockIdx.x * 128;

    const float4* X4 = (const float4*)X;
    for (int i = tid; i < 2048; i += 128) {
        int row = i >> 4, k4 = i & 15;
        float4 v = make_float4(0.f, 0.f, 0.f, 0.f);
        if (rbase + row < N) v = X4[(size_t)(rbase + row) * 16 + k4];
        float* p = sX + row * SXS + k4 * 4;
        p[0] = v.x; p[1] = v.y; p[2] = v.z; p[3] = v.w;
    }
    for (int i = tid; i < 64 * KOUT / 4; i += 128)
        ((float4*)sW)[i] = ((const float4*)W)[i];
    __syncthreads();

    int ty = tid >> 3, tx = tid & 7;      // ty 0..15, rows ty + 16*i
    const float* ap = sX + ty * SXS;
    const float* wp = sW + tx * 8;

    float acc[8][8];
#pragma unroll
    for (int i = 0; i < 8; i++)
#pragma unroll
        for (int j = 0; j < 8; j++) acc[i][j] = 0.f;

#pragma unroll 4
    for (int kk = 0; kk < 32; kk++) {
        int k = kk * 2;
        float2 a[8];
#pragma unroll
        for (int i = 0; i < 8; i++)
            a[i] = *(const float2*)(ap + (i * 16) * SXS + k);
        float4 wa0 = *(const float4*)(wp + (size_t)k * KOUT);
        float4 wb0 = *(const float4*)(wp + (size_t)k * KOUT + 4);
        float4 wa1 = *(const float4*)(wp + (size_t)(k + 1) * KOUT);
        float4 wb1 = *(const float4*)(wp + (size_t)(k + 1) * KOUT + 4);
        float w0[8] = {wa0.x, wa0.y, wa0.z, wa0.w, wb0.x, wb0.y, wb0.z, wb0.w};
        float w1[8] = {wa1.x, wa1.y, wa1.z, wa1.w, wb1.x, wb1.y, wb1.z, wb1.w};
#pragma unroll
        for (int i = 0; i < 8; i++)
#pragma unroll
            for (int j = 0; j < 8; j++) {
                acc[i][j] = fmaf(a[i].x, w0[j], acc[i][j]);
                acc[i][j] = fmaf(a[i].y, w1[j], acc[i][j]);
            }
    }

#pragma unroll
    for (int i = 0; i < 8; i++) {
        int row = rbase + ty + i * 16;
        if (row < N) {
            __half* yr = Y + (size_t)row * 64 + tx * 8;
            union { uint4 u; __half2 h[4]; } pk;
#pragma unroll
            for (int j = 0; j < 4; j++)
                pk.h[j] = __floats2half2_rn(acc[i][2 * j], acc[i][2 * j + 1]);
            *(uint4*)yr = pk.u;
        }
    }
}

// ------------------------------ SpMM (R5-proven) --------------------
__global__ void k_spmm64h(const __half2* __restrict__ g,
                          const float* __restrict__ bias,
                          float* __restrict__ out, int N, int doRelu) {
    const unsigned FULL = 0xffffffffu;
    int w = (blockIdx.x * blockDim.x + threadIdx.x) >> 5;
    int lane = threadIdx.x & 31;
    if (w >= N) return;
    int beg = g_rowptr[w], end = g_rowptr[w + 1];
    float2 acc = make_float2(0.f, 0.f);
    for (int i = beg; i < end; i += 32) {
        int n = end - i; if (n > 32) n = 32;
        int sidx = g_csr[i + (lane < n ? lane : 0)];
        int j = 0;
        for (; j + 8 <= n; j += 8) {
            int s[8];
#pragma unroll
            for (int u = 0; u < 8; u++) s[u] = __shfl_sync(FULL, sidx, j + u);
            __half2 v[8];
#pragma unroll
            for (int u = 0; u < 8; u++) v[u] = g[(size_t)s[u] * 32 + lane];
#pragma unroll
            for (int u = 0; u < 8; u++) {
                float2 f = __half22float2(v[u]);
                acc.x += f.x; acc.y += f.y;
            }
        }
        for (; j < n; j++) {
            int s = __shfl_sync(FULL, sidx, j);
            float2 f = __half22float2(g[(size_t)s * 32 + lane]);
            acc.x += f.x; acc.y += f.y;
        }
    }
    float2 b = ((const float2*)bias)[lane];
    acc.x += b.x; acc.y += b.y;
    if (doRelu) { acc.x = fmaxf(acc.x, 0.f); acc.y = fmaxf(acc.y, 0.f); }
    ((float2*)out)[(size_t)w * 32 + lane] = acc;
}

__global__ void k_spmm40h(const __half2* __restrict__ g,
                          const float* __restrict__ bias,
                          float* __restrict__ out, int N) {
    const unsigned FULL = 0xffffffffu;
    int w = (blockIdx.x * blockDim.x + threadIdx.x) >> 5;
    int lane = threadIdx.x & 31;
    if (w >= N) return;
    int beg = g_rowptr[w], end = g_rowptr[w + 1];
    float2 acc = make_float2(0.f, 0.f);
    bool act = (lane < NCLS / 2);
    for (int i = beg; i < end; i += 32) {
        int n = end - i; if (n > 32) n = 32;
        int sidx = g_csr[i + (lane < n ? lane : 0)];
        int j = 0;
        for (; j + 8 <= n; j += 8) {
            int s[8];
#pragma unroll
            for (int u = 0; u < 8; u++) s[u] = __shfl_sync(FULL, sidx, j + u);
            if (act) {
                __half2 v[8];
#pragma unroll
                for (int u = 0; u < 8; u++) v[u] = g[(size_t)s[u] * 32 + lane];
#pragma unroll
                for (int u = 0; u < 8; u++) {
                    float2 f = __half22float2(v[u]);
                    acc.x += f.x; acc.y += f.y;
                }
            }
        }
        for (; j < n; j++) {
            int s = __shfl_sync(FULL, sidx, j);
            if (act) {
                float2 f = __half22float2(g[(size_t)s * 32 + lane]);
                acc.x += f.x; acc.y += f.y;
            }
        }
    }
    if (act) {
        float2 b = ((const float2*)bias)[lane];
        acc.x += b.x; acc.y += b.y;
        ((float2*)(out + (size_t)w * NCLS))[lane] = acc;
    }
}

// ---------------------- axis-0 log-softmax + loss -------------------
__device__ __forceinline__ void msmerge(float& M, float& S, float m2, float s2) {
    if (m2 > M) { S = S * fexp(M - m2) + s2; M = m2; }
    else if (m2 > -INFINITY) S += s2 * fexp(m2 - M);
}

__global__ void k_colreduce(const float* __restrict__ rep, int N) {
    int col = threadIdx.x % NCLS;
    int sub = threadIdx.x / NCLS;
    float m = -INFINITY, s = 0.f;
    for (int r = blockIdx.x * 8 + sub; r < N; r += 8 * gridDim.x) {
        float x = rep[(size_t)r * NCLS + col];
        if (x > m) { s = s * fexp(m - x) + 1.f; m = x; }
        else s += fexp(x - m);
    }
    __shared__ float shm[320], shs[320];
    shm[threadIdx.x] = m; shs[threadIdx.x] = s;
    __syncthreads();
    if (sub == 0) {
        float M = m, S = s;
        for (int k = 1; k < 8; k++) msmerge(M, S, shm[k * NCLS + col], shs[k * NCLS + col]);
        g_pM[blockIdx.x * NCLS + col] = M;
        g_pS[blockIdx.x * NCLS + col] = S;
    }
}

__global__ void k_colfinal() {
    int col = threadIdx.x;
    if (col >= NCLS) return;
    float M = -INFINITY, S = 0.f;
    for (int b = 0; b < GRED; b++) msmerge(M, S, g_pM[b * NCLS + col], g_pS[b * NCLS + col]);
    g_logZ[col] = M + logf(S);
}

__global__ void k_loss(const float* __restrict__ rep,
                       const int* __restrict__ labels,
                       const int* __restrict__ mask, int N,
                       float* __restrict__ out_loss) {
    float lp = 0.f, lm = 0.f;
    for (int n = blockIdx.x * blockDim.x + threadIdx.x; n < N;
         n += gridDim.x * blockDim.x) {
        if (mask[n] != 0) {
            int l = labels[n];
            lp += rep[(size_t)n * NCLS + l] - g_logZ[l];
            lm += 1.f;
        }
    }
    __shared__ float sp[256], sm[256];
    sp[threadIdx.x] = lp; sm[threadIdx.x] = lm;
    __syncthreads();
    for (int off = 128; off > 0; off >>= 1) {
        if (threadIdx.x < off) {
            sp[threadIdx.x] += sp[threadIdx.x + off];
            sm[threadIdx.x] += sm[threadIdx.x + off];
        }
        __syncthreads();
    }
    if (threadIdx.x == 0) {
        atomicAdd(&g_loss[0], sp[0]);
        atomicAdd(&g_loss[1], sm[0]);
        __threadfence();
        int done = atomicAdd(&g_ctr, 1);
        if (done == gridDim.x - 1 && out_loss)
            *out_loss = -g_loss[0] / g_loss[1];
    }
}

// ------------------------------ launch ------------------------------
extern "C" void kernel_launch(void* const* d_in, const int* in_sizes, int n_in,
                              void* d_out, int out_size) {
    const float* features = (const float*)d_in[0];
    const float* W0 = (const float*)d_in[1];
    const float* b0 = (const float*)d_in[2];
    const float* W1 = (const float*)d_in[3];
    const float* b1 = (const float*)d_in[4];
    const float* W2 = (const float*)d_in[5];
    const float* b2 = (const float*)d_in[6];
    const int*   src = (const int*)d_in[7];
    const int*   dst = (const int*)d_in[8];
    const int*   labels = (const int*)d_in[9];
    const int*   mask = (const int*)d_in[10];

    int N = in_sizes[0] / HID;
    int E = in_sizes[7];
    if (N > NMAX) N = NMAX;
    if (E > EMAX) E = EMAX;

    float* rep = (float*)d_out;
    float* lossptr = (out_size > N * NCLS) ? rep + (size_t)N * NCLS : nullptr;

    __half* gbuf; cudaGetSymbolAddress((void**)&gbuf, g_buf);
    float*  hbuf; cudaGetSymbolAddress((void**)&hbuf, g_hbuf);
    float*  w2p;  cudaGetSymbolAddress((void**)&w2p,  g_W2p);

    const int SM64 = (128 * 66 + 64 * 64) * 4;
    cudaFuncSetAttribute(k_gemm_rt, cudaFuncAttributeMaxDynamicSharedMemorySize, SM64);

    int NB = (N + SCAN_B - 1) / SCAN_B;
    int gemmBlocks = (N + 127) / 128;
    int spmmBlocks = (N * 32 + 255) / 256;

    // CSR build; gemm0 at launch slot 3 (ncu profiles the fixed GEMM)
    k_init<<<(N + 255) / 256, 256>>>(N);
    k_hist<<<1024, 256>>>(dst, E);
    k_scan<<<NB, SCAN_B>>>(N);
    k_gemm_rt<<<gemmBlocks, 128, SM64>>>(features, W0, gbuf, N);
    k_scatter<<<1024, 256>>>(src, dst, E);
    k_w2pad<<<16, 256>>>(W2);

    // Layer 0 aggregate
    k_spmm64h<<<spmmBlocks, 256>>>((const __half2*)gbuf, b0, hbuf, N, 1);
    // Layer 1
    k_gemm_rt<<<gemmBlocks, 128, SM64>>>(hbuf, W1, gbuf, N);
    k_spmm64h<<<spmmBlocks, 256>>>((const __half2*)gbuf, b1, hbuf, N, 1);
    // Layer 2 (W2 padded to 64 cols; output 40-wide)
    k_gemm_rt<<<gemmBlocks, 128, SM64>>>(hbuf, w2p, gbuf, N);
    k_spmm40h<<<spmmBlocks, 256>>>((const __half2*)gbuf, b2, rep, N);

    // axis-0 log-softmax + NLL loss
    k_colreduce<<<GRED, 320>>>(rep, N);
    k_colfinal<<<1, 64>>>();
    k_loss<<<256, 256>>>(rep, labels, mask, N, lossptr);
}

// round 9
// speedup vs baseline: 1.3140x; 1.1648x over previous
#include <cuda_runtime.h>
#include <cuda_fp16.h>
#include <math.h>

#define NMAX 100000
#define NPAD 100096          // 391 * 256, allows guard-free 256-row GEMM blocks
#define EMAX 1700000
#define HID  64
#define NCLS 40
#define GRED 256
#define SCAN_B 1024

// -------- scratch (device globals: no allocations allowed) --------
__device__ int      g_rowptr[NMAX + 1];
__device__ int      g_cnt[NMAX];
__device__ int      g_csr[EMAX];
__device__ unsigned g_scan_state[128];
__device__ int      g_ctr;
__device__ __half   g_buf[NPAD * HID];   // GEMM outputs (SpMM gather source)
__device__ __half   g_hb [NPAD * HID];   // fp16 activations / converted X
__device__ __half   g_wt [3 * 4096];     // W0,W1,W2 transposed fp16: wt[w][j*64+k]=W[k][j]
__device__ float    g_pM[GRED * NCLS];
__device__ float    g_pS[GRED * NCLS];
__device__ float    g_logZ[NCLS];
__device__ float    g_loss[2];

// ---------------------- fast exp (FMA pipe, x <= 0) ------------------
__device__ __forceinline__ float fexp(float x) {
    x = fmaxf(x, -80.0f);
    float y = x * 1.44269504f;
    int   ni = __float2int_rn(y);
    float f = y - (float)ni;
    float g = f * 0.69314718f;
    float p = fmaf(g, 1.3888889e-3f, 8.3333333e-3f);
    p = fmaf(p, g, 4.1666667e-2f);
    p = fmaf(p, g, 1.6666667e-1f);
    p = fmaf(p, g, 0.5f);
    p = fmaf(p, g, 1.0f);
    p = fmaf(p, g, 1.0f);
    return p * __int_as_float((ni + 127) << 23);
}

// ------------------------------- init -------------------------------
__global__ void k_init(int N) {
    int i = blockIdx.x * blockDim.x + threadIdx.x;
    if (i < N) g_cnt[i] = 0;
    if (i < 128) g_scan_state[i] = 0u;
    if (i == 0) { g_loss[0] = 0.f; g_loss[1] = 0.f; g_ctr = 0; }
}

// --------------------------- CSR build ------------------------------
__global__ void k_hist(const int* __restrict__ dst, int E) {
    int stride = gridDim.x * blockDim.x;
    int i = blockIdx.x * blockDim.x + threadIdx.x;
    int E4 = E >> 2;
    for (int e = i; e < E4; e += stride) {
        int4 d = ((const int4*)dst)[e];
        atomicAdd(&g_cnt[d.x], 1);
        atomicAdd(&g_cnt[d.y], 1);
        atomicAdd(&g_cnt[d.z], 1);
        atomicAdd(&g_cnt[d.w], 1);
    }
    int tail = E4 * 4 + i;
    if (tail < E) atomicAdd(&g_cnt[dst[tail]], 1);
}

// fp32->fp16 conversion: X -> g_hb, all W -> g_wt (transposed, W2 padded)
__global__ void k_conv(const float4* __restrict__ X4, int nx4,
                       const float* __restrict__ W0,
                       const float* __restrict__ W1,
                       const float* __restrict__ W2) {
    int stride = gridDim.x * blockDim.x;
    int i0 = blockIdx.x * blockDim.x + threadIdx.x;
    for (int i = i0; i < nx4; i += stride) {
        float4 v = X4[i];
        __half2* o = ((__half2*)g_hb) + i * 2;
        o[0] = __floats2half2_rn(v.x, v.y);
        o[1] = __floats2half2_rn(v.z, v.w);
    }
    if (i0 < 3 * 4096) {
        int w = i0 >> 12, r = i0 & 4095;
        int j = r >> 6, k = r & 63;
        float val;
        if (w == 0)      val = W0[k * 64 + j];
        else if (w == 1) val = W1[k * 64 + j];
        else             val = (j < NCLS) ? W2[k * NCLS + j] : 0.f;
        g_wt[i0] = __float2half_rn(val);
    }
}

// single-pass exclusive scan with decoupled lookback (unsigned flags)
__global__ void k_scan(int N) {
    __shared__ int sh[SCAN_B];
    __shared__ int s_prefix;
    const unsigned FULL = 0xffffffffu;
    int b = blockIdx.x;
    int i = b * SCAN_B + threadIdx.x;
    int c = (i < N) ? g_cnt[i] : 0;
    sh[threadIdx.x] = c;
    __syncthreads();
    for (int off = 1; off < SCAN_B; off <<= 1) {
        int t = (threadIdx.x >= off) ? sh[threadIdx.x - off] : 0;
        __syncthreads();
        sh[threadIdx.x] += t;
        __syncthreads();
    }
    int incl = sh[threadIdx.x];
    int agg  = sh[SCAN_B - 1];

    if (threadIdx.x == 0) {
        if (b == 0) {
            s_prefix = 0;
            atomicExch(&g_scan_state[0], 0x80000000u | (unsigned)agg);
        } else {
            atomicExch(&g_scan_state[b], 0x40000000u | (unsigned)agg);
        }
    }
    if (b > 0 && threadIdx.x < 32) {
        int lane = threadIdx.x;
        int prefix = 0;
        int look = b - 1;
        while (true) {
            int idxb = look - lane;
            unsigned st;
            if (idxb >= 0) {
                do { st = atomicAdd(&g_scan_state[idxb], 0u); } while ((st >> 30) == 0u);
            } else {
                st = 0x80000000u;
            }
            int val = (int)(st & 0x3FFFFFFFu);
            unsigned m2 = __ballot_sync(FULL, (st >> 30) == 2u);
            if (m2 == 0u) {
                int s = val;
                for (int o = 16; o; o >>= 1) s += __shfl_xor_sync(FULL, s, o);
                prefix += s;
                look -= 32;
            } else {
                int firstIncl = __ffs(m2) - 1;
                int s = (lane <= firstIncl) ? val : 0;
                for (int o = 16; o; o >>= 1) s += __shfl_xor_sync(FULL, s, o);
                prefix += s;
                break;
            }
        }
        if (lane == 0) {
            atomicExch(&g_scan_state[b], 0x80000000u | (unsigned)(prefix + agg));
            s_prefix = prefix;
        }
    }
    __syncthreads();
    int base = s_prefix;
    int excl = base + incl - c;
    if (i < N) { g_rowptr[i] = excl; g_cnt[i] = excl; }
    if (i == N - 1) g_rowptr[N] = base + incl;
}

__global__ void k_scatter(const int* __restrict__ src,
                          const int* __restrict__ dst, int E) {
    int stride = gridDim.x * blockDim.x;
    int i = blockIdx.x * blockDim.x + threadIdx.x;
    int E4 = E >> 2;
    for (int e = i; e < E4; e += stride) {
        int4 d = ((const int4*)dst)[e];
        int4 s = ((const int4*)src)[e];
        g_csr[atomicAdd(&g_cnt[d.x], 1)] = s.x;
        g_csr[atomicAdd(&g_cnt[d.y], 1)] = s.y;
        g_csr[atomicAdd(&g_cnt[d.z], 1)] = s.z;
        g_csr[atomicAdd(&g_cnt[d.w], 1)] = s.w;
    }
    int tail = E4 * 4 + i;
    if (tail < E)
        g_csr[atomicAdd(&g_cnt[dst[tail]], 1)] = src[tail];
}

// --------------------- tensor-core GEMM (HMMA) ----------------------
// Y[NPAD,64] = A[NPAD,64] @ W[64,64], all fp16, fp32 accum.
// Wt is W transposed (wt[j*64+k] = W[k][j]). Block = 128 thr = 4 warps,
// 256 rows/block (4 iters x 4 warps x 16 rows). W frags register-resident,
// loaded once from stride-66 smem (bank-conflict-free).
__device__ __forceinline__ void mma16816(float c[4], const unsigned a[4],
                                         const unsigned b0, const unsigned b1) {
    asm volatile(
        "mma.sync.aligned.m16n8k16.row.col.f32.f16.f16.f32 "
        "{%0,%1,%2,%3}, {%4,%5,%6,%7}, {%8,%9}, {%0,%1,%2,%3};\n"
        : "+f"(c[0]), "+f"(c[1]), "+f"(c[2]), "+f"(c[3])
        : "r"(a[0]), "r"(a[1]), "r"(a[2]), "r"(a[3]), "r"(b0), "r"(b1));
}

__global__ __launch_bounds__(128) void k_gemm_mma(
    const __half* __restrict__ A, const __half* __restrict__ Wt,
    __half* __restrict__ Y) {
    __shared__ __half sW[64 * 66];
    int tid = threadIdx.x;
    for (int i = tid; i < 4096; i += 128)
        sW[(i >> 6) * 66 + (i & 63)] = Wt[i];
    __syncthreads();

    int lane = tid & 31, warp = tid >> 5;
    int g = lane >> 2, tg = lane & 3;

    unsigned b[4][8][2];
#pragma unroll
    for (int kc = 0; kc < 4; kc++)
#pragma unroll
        for (int nt = 0; nt < 8; nt++) {
            const __half* p = sW + (nt * 8 + g) * 66 + kc * 16 + tg * 2;
            b[kc][nt][0] = *(const unsigned*)p;
            b[kc][nt][1] = *(const unsigned*)(p + 8);
        }

    size_t rowbase = (size_t)blockIdx.x * 256 + warp * 16;
#pragma unroll
    for (int it = 0; it < 4; it++) {
        size_t r0 = rowbase + (size_t)it * 64;
        const __half* a0p = A + (r0 + g) * 64 + tg * 2;
        const __half* a1p = A + (r0 + g + 8) * 64 + tg * 2;
        float c[8][4];
#pragma unroll
        for (int nt = 0; nt < 8; nt++)
#pragma unroll
            for (int q = 0; q < 4; q++) c[nt][q] = 0.f;
#pragma unroll
        for (int kc = 0; kc < 4; kc++) {
            unsigned a[4];
            a[0] = *(const unsigned*)(a0p + kc * 16);
            a[1] = *(const unsigned*)(a1p + kc * 16);
            a[2] = *(const unsigned*)(a0p + kc * 16 + 8);
            a[3] = *(const unsigned*)(a1p + kc * 16 + 8);
#pragma unroll
            for (int nt = 0; nt < 8; nt++)
                mma16816(c[nt], a, b[kc][nt][0], b[kc][nt][1]);
        }
        __half* y0 = Y + (r0 + g) * 64 + tg * 2;
        __half* y1 = Y + (r0 + g + 8) * 64 + tg * 2;
#pragma unroll
        for (int nt = 0; nt < 8; nt++) {
            *(__half2*)(y0 + nt * 8) = __floats2half2_rn(c[nt][0], c[nt][1]);
            *(__half2*)(y1 + nt * 8) = __floats2half2_rn(c[nt][2], c[nt][3]);
        }
    }
}

// ------------------------------ SpMM --------------------------------
// out (fp16) [v,:] = relu( sum g[src,:] + bias )
__global__ void k_spmm64h(const __half2* __restrict__ g,
                          const float* __restrict__ bias,
                          __half2* __restrict__ out, int N) {
    const unsigned FULL = 0xffffffffu;
    int w = (blockIdx.x * blockDim.x + threadIdx.x) >> 5;
    int lane = threadIdx.x & 31;
    if (w >= N) return;
    int beg = g_rowptr[w], end = g_rowptr[w + 1];
    float2 acc = make_float2(0.f, 0.f);
    for (int i = beg; i < end; i += 32) {
        int n = end - i; if (n > 32) n = 32;
        int sidx = g_csr[i + (lane < n ? lane : 0)];
        int j = 0;
        for (; j + 8 <= n; j += 8) {
            int s[8];
#pragma unroll
            for (int u = 0; u < 8; u++) s[u] = __shfl_sync(FULL, sidx, j + u);
            __half2 v[8];
#pragma unroll
            for (int u = 0; u < 8; u++) v[u] = g[(size_t)s[u] * 32 + lane];
#pragma unroll
            for (int u = 0; u < 8; u++) {
                float2 f = __half22float2(v[u]);
                acc.x += f.x; acc.y += f.y;
            }
        }
        for (; j < n; j++) {
            int s = __shfl_sync(FULL, sidx, j);
            float2 f = __half22float2(g[(size_t)s * 32 + lane]);
            acc.x += f.x; acc.y += f.y;
        }
    }
    float2 b = ((const float2*)bias)[lane];
    acc.x = fmaxf(acc.x + b.x, 0.f);
    acc.y = fmaxf(acc.y + b.y, 0.f);
    out[(size_t)w * 32 + lane] = __floats2half2_rn(acc.x, acc.y);
}

// final 40-wide aggregation -> fp32 rep
__global__ void k_spmm40h(const __half2* __restrict__ g,
                          const float* __restrict__ bias,
                          float* __restrict__ out, int N) {
    const unsigned FULL = 0xffffffffu;
    int w = (blockIdx.x * blockDim.x + threadIdx.x) >> 5;
    int lane = threadIdx.x & 31;
    if (w >= N) return;
    int beg = g_rowptr[w], end = g_rowptr[w + 1];
    float2 acc = make_float2(0.f, 0.f);
    bool act = (lane < NCLS / 2);
    for (int i = beg; i < end; i += 32) {
        int n = end - i; if (n > 32) n = 32;
        int sidx = g_csr[i + (lane < n ? lane : 0)];
        int j = 0;
        for (; j + 8 <= n; j += 8) {
            int s[8];
#pragma unroll
            for (int u = 0; u < 8; u++) s[u] = __shfl_sync(FULL, sidx, j + u);
            if (act) {
                __half2 v[8];
#pragma unroll
                for (int u = 0; u < 8; u++) v[u] = g[(size_t)s[u] * 32 + lane];
#pragma unroll
                for (int u = 0; u < 8; u++) {
                    float2 f = __half22float2(v[u]);
                    acc.x += f.x; acc.y += f.y;
                }
            }
        }
        for (; j < n; j++) {
            int s = __shfl_sync(FULL, sidx, j);
            if (act) {
                float2 f = __half22float2(g[(size_t)s * 32 + lane]);
                acc.x += f.x; acc.y += f.y;
            }
        }
    }
    if (act) {
        float2 b = ((const float2*)bias)[lane];
        acc.x += b.x; acc.y += b.y;
        ((float2*)(out + (size_t)w * NCLS))[lane] = acc;
    }
}

// ---------------------- axis-0 log-softmax + loss -------------------
__device__ __forceinline__ void msmerge(float& M, float& S, float m2, float s2) {
    if (m2 > M) { S = S * fexp(M - m2) + s2; M = m2; }
    else if (m2 > -INFINITY) S += s2 * fexp(m2 - M);
}

__global__ void k_colreduce(const float* __restrict__ rep, int N) {
    int col = threadIdx.x % NCLS;
    int sub = threadIdx.x / NCLS;
    float m = -INFINITY, s = 0.f;
    for (int r = blockIdx.x * 8 + sub; r < N; r += 8 * gridDim.x) {
        float x = rep[(size_t)r * NCLS + col];
        if (x > m) { s = s * fexp(m - x) + 1.f; m = x; }
        else s += fexp(x - m);
    }
    __shared__ float shm[320], shs[320];
    shm[threadIdx.x] = m; shs[threadIdx.x] = s;
    __syncthreads();
    if (sub == 0) {
        float M = m, S = s;
        for (int k = 1; k < 8; k++) msmerge(M, S, shm[k * NCLS + col], shs[k * NCLS + col]);
        g_pM[blockIdx.x * NCLS + col] = M;
        g_pS[blockIdx.x * NCLS + col] = S;
    }
}

__global__ void k_colfinal() {
    int col = threadIdx.x;
    if (col >= NCLS) return;
    float M = -INFINITY, S = 0.f;
    for (int b = 0; b < GRED; b++) msmerge(M, S, g_pM[b * NCLS + col], g_pS[b * NCLS + col]);
    g_logZ[col] = M + logf(S);
}

__global__ void k_loss(const float* __restrict__ rep,
                       const int* __restrict__ labels,
                       const int* __restrict__ mask, int N,
                       float* __restrict__ out_loss) {
    float lp = 0.f, lm = 0.f;
    for (int n = blockIdx.x * blockDim.x + threadIdx.x; n < N;
         n += gridDim.x * blockDim.x) {
        if (mask[n] != 0) {
            int l = labels[n];
            lp += rep[(size_t)n * NCLS + l] - g_logZ[l];
            lm += 1.f;
        }
    }
    __shared__ float sp[256], sm[256];
    sp[threadIdx.x] = lp; sm[threadIdx.x] = lm;
    __syncthreads();
    for (int off = 128; off > 0; off >>= 1) {
        if (threadIdx.x < off) {
            sp[threadIdx.x] += sp[threadIdx.x + off];
            sm[threadIdx.x] += sm[threadIdx.x + off];
        }
        __syncthreads();
    }
    if (threadIdx.x == 0) {
        atomicAdd(&g_loss[0], sp[0]);
        atomicAdd(&g_loss[1], sm[0]);
        __threadfence();
        int done = atomicAdd(&g_ctr, 1);
        if (done == gridDim.x - 1 && out_loss)
            *out_loss = -g_loss[0] / g_loss[1];
    }
}

// ------------------------------ launch ------------------------------
extern "C" void kernel_launch(void* const* d_in, const int* in_sizes, int n_in,
                              void* d_out, int out_size) {
    const float* features = (const float*)d_in[0];
    const float* W0 = (const float*)d_in[1];
    const float* b0 = (const float*)d_in[2];
    const float* W1 = (const float*)d_in[3];
    const float* b1 = (const float*)d_in[4];
    const float* W2 = (const float*)d_in[5];
    const float* b2 = (const float*)d_in[6];
    const int*   src = (const int*)d_in[7];
    const int*   dst = (const int*)d_in[8];
    const int*   labels = (const int*)d_in[9];
    const int*   mask = (const int*)d_in[10];

    int N = in_sizes[0] / HID;
    int E = in_sizes[7];
    if (N > NMAX) N = NMAX;
    if (E > EMAX) E = EMAX;

    float* rep = (float*)d_out;
    float* lossptr = (out_size > N * NCLS) ? rep + (size_t)N * NCLS : nullptr;

    __half* gbuf; cudaGetSymbolAddress((void**)&gbuf, g_buf);
    __half* hb;   cudaGetSymbolAddress((void**)&hb,   g_hb);
    __half* wt;   cudaGetSymbolAddress((void**)&wt,   g_wt);

    int NB = (N + SCAN_B - 1) / SCAN_B;
    int gemmBlocks = (N + 255) / 256;
    int spmmBlocks = (N * 32 + 255) / 256;

    // 0:init 1:hist 2:conv 3:gemm0(profiled) 4:scan 5:scatter ...
    k_init<<<(N + 255) / 256, 256>>>(N);
    k_hist<<<1024, 256>>>(dst, E);
    k_conv<<<1024, 256>>>((const float4*)features, N * 16, W0, W1, W2);
    k_gemm_mma<<<gemmBlocks, 128>>>(hb, wt, gbuf);
    k_scan<<<NB, SCAN_B>>>(N);
    k_scatter<<<1024, 256>>>(src, dst, E);

    // Layer 0 aggregate -> fp16 activations
    k_spmm64h<<<spmmBlocks, 256>>>((const __half2*)gbuf, b0, (__half2*)hb, N);
    // Layer 1
    k_gemm_mma<<<gemmBlocks, 128>>>(hb, wt + 4096, gbuf);
    k_spmm64h<<<spmmBlocks, 256>>>((const __half2*)gbuf, b1, (__half2*)hb, N);
    // Layer 2 (padded W2)
    k_gemm_mma<<<gemmBlocks, 128>>>(hb, wt + 8192, gbuf);
    k_spmm40h<<<spmmBlocks, 256>>>((const __half2*)gbuf, b2, rep, N);

    // axis-0 log-softmax + NLL loss
    k_colreduce<<<GRED, 320>>>(rep, N);
    k_colfinal<<<1, 64>>>();
    k_loss<<<256, 256>>>(rep, labels, mask, N, lossptr);
}